// round 10
// baseline (speedup 1.0000x reference)
#include <cuda_runtime.h>
#include <cuda_bf16.h>
#include <cuda_fp16.h>
#include <cstdint>

// ---------------- problem constants ----------------
#define N_NODES 4096
#define F_IN    512
#define N_HEADS 4
#define N_HID   256
#define HD      1024     // N_HEADS*N_HID == GEMM2 N (head-interleaved)

// ---------------- scratch (device globals; allocation-free) ----------------
__device__ uint16_t g_hh [N_NODES * F_IN];             // fp16 hi of h
__device__ uint16_t g_hl [N_NODES * F_IN];             // fp16 lo of h
__device__ uint16_t g_Wh [F_IN * HD];                  // fp16 W
__device__ uint16_t g_adjh[(size_t)N_NODES * N_NODES]; // fp16 adjacency {0,1}
__device__ uint16_t g_V  [(size_t)N_NODES * HD];       // fp16 weighted V, col = 4d+h
__device__ float    g_HT [N_NODES * HD];               // h@W fp32
__device__ float    g_tgt [N_HEADS * N_NODES];
__device__ float    g_tmax[N_HEADS];
__device__ float4   g_w4 [N_NODES];                    // per-node head weights (scaled exp)
__device__ float4   g_Z4 [N_NODES];                    // denominators (exact fp32)

// ---------------- small helpers ----------------
__device__ __forceinline__ uint32_t smem_u32(const void* p) {
    uint32_t a;
    asm("{ .reg .u64 t; cvta.to.shared.u64 t, %1; cvt.u32.u64 %0, t; }" : "=r"(a) : "l"(p));
    return a;
}
__device__ __forceinline__ uint32_t pk(uint16_t a, uint16_t b) {
    return (uint32_t)a | ((uint32_t)b << 16);
}
__device__ __forceinline__ void cpasync16(uint32_t dst, const void* src) {
    asm volatile("cp.async.cg.shared.global [%0], [%1], 16;" :: "r"(dst), "l"(src));
}
__device__ __forceinline__ void cp_commit() {
    asm volatile("cp.async.commit_group;" ::: "memory");
}
template <int N>
__device__ __forceinline__ void cp_wait() {
    asm volatile("cp.async.wait_group %0;" :: "n"(N) : "memory");
}
__device__ __forceinline__ void ldsm4(uint32_t& r0, uint32_t& r1, uint32_t& r2, uint32_t& r3,
                                      uint32_t addr) {
    asm volatile("ldmatrix.sync.aligned.m8n8.x4.shared.b16 {%0,%1,%2,%3}, [%4];"
                 : "=r"(r0), "=r"(r1), "=r"(r2), "=r"(r3) : "r"(addr));
}
__device__ __forceinline__ void ldsm4t(uint32_t& r0, uint32_t& r1, uint32_t& r2, uint32_t& r3,
                                       uint32_t addr) {
    asm volatile("ldmatrix.sync.aligned.m8n8.x4.trans.shared.b16 {%0,%1,%2,%3}, [%4];"
                 : "=r"(r0), "=r"(r1), "=r"(r2), "=r"(r3) : "r"(addr));
}
__device__ __forceinline__ void mma16816(float* c, const uint32_t* a, const uint32_t* b) {
    asm volatile(
        "mma.sync.aligned.m16n8k16.row.col.f32.f16.f16.f32 "
        "{%0,%1,%2,%3},{%4,%5,%6,%7},{%8,%9},{%0,%1,%2,%3};"
        : "+f"(c[0]), "+f"(c[1]), "+f"(c[2]), "+f"(c[3])
        : "r"(a[0]), "r"(a[1]), "r"(a[2]), "r"(a[3]), "r"(b[0]), "r"(b[1]));
}

// ---------------- prep kernels ----------------
__global__ void split_h16(const float4* __restrict__ src,
                          uint4* __restrict__ hh, uint4* __restrict__ hl) {
    int i = blockIdx.x * 256 + threadIdx.x;
    float4 v0 = src[2 * i], v1 = src[2 * i + 1];
    float f[8] = {v0.x, v0.y, v0.z, v0.w, v1.x, v1.y, v1.z, v1.w};
    uint16_t H[8], L[8];
    #pragma unroll
    for (int j = 0; j < 8; j++) {
        __half b = __float2half_rn(f[j]);
        H[j] = __half_as_ushort(b);
        L[j] = __half_as_ushort(__float2half_rn(f[j] - __half2float(b)));
    }
    hh[i] = make_uint4(pk(H[0], H[1]), pk(H[2], H[3]), pk(H[4], H[5]), pk(H[6], H[7]));
    hl[i] = make_uint4(pk(L[0], L[1]), pk(L[2], L[3]), pk(L[4], L[5]), pk(L[6], L[7]));
}

__global__ void cvt_f16(const float4* __restrict__ src, uint4* __restrict__ dst) {
    int i = blockIdx.x * 256 + threadIdx.x;
    float4 v0 = src[2 * i], v1 = src[2 * i + 1];
    float f[8] = {v0.x, v0.y, v0.z, v0.w, v1.x, v1.y, v1.z, v1.w};
    uint16_t H[8];
    #pragma unroll
    for (int j = 0; j < 8; j++) H[j] = __half_as_ushort(__float2half_rn(f[j]));
    dst[i] = make_uint4(pk(H[0], H[1]), pk(H[2], H[3]), pk(H[4], H[5]), pk(H[6], H[7]));
}

__global__ void tgt_kernel(const float* __restrict__ HT, const float* __restrict__ a,
                           float* __restrict__ tgt) {
    int warp = (blockIdx.x * blockDim.x + threadIdx.x) >> 5;
    int lane = threadIdx.x & 31;
    if (warp >= N_HEADS * N_NODES) return;
    int h = warp >> 12, m = warp & 4095;
    const float* row = HT + (size_t)m * HD + h * N_HID;
    const float* av  = a + h * (2 * N_HID) + N_HID;
    float s = 0.0f;
    #pragma unroll
    for (int d = lane; d < N_HID; d += 32) {
        float x = row[d];
        x = (x > 0.0f) ? x : 0.1f * x;
        s += x * av[d];
    }
    #pragma unroll
    for (int o = 16; o; o >>= 1) s += __shfl_xor_sync(0xFFFFFFFFu, s, o);
    if (lane == 0) tgt[h * N_NODES + m] = s;
}

__global__ void tmax_kernel(const float* __restrict__ tgt, float* __restrict__ tmax) {
    int h = blockIdx.x;
    __shared__ float sm[256];
    float m = -1e30f;
    for (int i = threadIdx.x; i < N_NODES; i += 256)
        m = fmaxf(m, tgt[h * N_NODES + i]);
    sm[threadIdx.x] = m;
    __syncthreads();
    for (int s = 128; s; s >>= 1) {
        if (threadIdx.x < s) sm[threadIdx.x] = fmaxf(sm[threadIdx.x], sm[threadIdx.x + s]);
        __syncthreads();
    }
    if (threadIdx.x == 0) tmax[h] = sm[0];
}

// per-node head weights: w = exp(tgt - tmax) * 4096  (scale cancels in ratio)
__global__ void prew_kernel(const float* __restrict__ tgt, const float* __restrict__ tmax,
                            float4* __restrict__ w4) {
    int n = blockIdx.x * 256 + threadIdx.x;
    float4 w;
    w.x = expf(tgt[0 * N_NODES + n] - tmax[0]) * 4096.0f;
    w.y = expf(tgt[1 * N_NODES + n] - tmax[1]) * 4096.0f;
    w.z = expf(tgt[2 * N_NODES + n] - tmax[2]) * 4096.0f;
    w.w = expf(tgt[3 * N_NODES + n] - tmax[3]) * 4096.0f;
    w4[n] = w;
}

// Fused adjacency pass: one streaming read of adj (int32) produces
//   adjh[m][n]  (fp16 {0,1}, GEMM2 A operand)
//   Z4[m]       (fp32 exact denominators: Z[m,h] = sum_n adj[m,n]*w[h,n])
// 8 warps/block, one m-row per warp; w staged in smem planes (bank = n%32 = lane).
__global__ void zconv_kernel(const int* __restrict__ adj, const float4* __restrict__ w4,
                             uint16_t* __restrict__ adjh, float4* __restrict__ Z4) {
    extern __shared__ float sw[];   // 4 planes x 4096 floats = 64 KB
    int tid = threadIdx.x, lane = tid & 31, wid = tid >> 5;
    for (int k = tid; k < N_NODES; k += 256) {
        float4 w = w4[k];
        sw[0 * N_NODES + k] = w.x;
        sw[1 * N_NODES + k] = w.y;
        sw[2 * N_NODES + k] = w.z;
        sw[3 * N_NODES + k] = w.w;
    }
    __syncthreads();
    int m = blockIdx.x * 8 + wid;
    const int* row = adj + (size_t)m * N_NODES;
    uint16_t* orow = adjh + (size_t)m * N_NODES;
    float a0 = 0.f, a1 = 0.f, a2 = 0.f, a3 = 0.f;
    #pragma unroll 4
    for (int j = 0; j < N_NODES / 32; j++) {
        int n = j * 32 + lane;
        int v = row[n];
        float msk = (v > 0) ? 1.0f : 0.0f;
        orow[n] = (v > 0) ? (uint16_t)0x3C00 : (uint16_t)0;
        a0 = fmaf(msk, sw[0 * N_NODES + n], a0);
        a1 = fmaf(msk, sw[1 * N_NODES + n], a1);
        a2 = fmaf(msk, sw[2 * N_NODES + n], a2);
        a3 = fmaf(msk, sw[3 * N_NODES + n], a3);
    }
    #pragma unroll
    for (int o = 16; o; o >>= 1) {
        a0 += __shfl_xor_sync(0xFFFFFFFFu, a0, o);
        a1 += __shfl_xor_sync(0xFFFFFFFFu, a1, o);
        a2 += __shfl_xor_sync(0xFFFFFFFFu, a2, o);
        a3 += __shfl_xor_sync(0xFFFFFFFFu, a3, o);
    }
    if (lane == 0) Z4[m] = make_float4(a0, a1, a2, a3);
}

// V[n, 4d+h] = w[h] * HT[n, h*256+d]   (fp16, head-interleaved columns)
__global__ void buildV(const float* __restrict__ HT, const float4* __restrict__ w4,
                       __half* __restrict__ V) {
    int n = blockIdx.x;
    float4 wv = w4[n];
    float wa[4] = {wv.x, wv.y, wv.z, wv.w};
    __half* row = V + (size_t)n * HD;
    const float* ht = HT + (size_t)n * HD;
    for (int c = threadIdx.x; c < HD; c += 256) {
        int d = c >> 2, h = c & 3;
        row[c] = __float2half(wa[h] * ht[h * N_HID + d]);
    }
}

// ---------------- shared GEMM geometry ----------------
#define BK 32
#define A_STRIDE 80                // bytes: 64B data + 16B pad per row
#define B_STRIDE 272               // bytes: 256B data + 16B pad per row
#define A_TILE1  (128 * A_STRIDE)  // 10240 B
#define B_TILE1  (BK * B_STRIDE)   // 8704 B

// ---------------- GEMM1: BM=128 BN=128, 8 warps (2x4), warp 64x32, NA=2 fp16 --------
template <int NA, int STAGES>
__global__ void __launch_bounds__(256, 2)
gemm_mma(const uint16_t* __restrict__ A1, const uint16_t* __restrict__ A2,
         const uint16_t* __restrict__ B1,
         float* __restrict__ C, int N, int K) {
    extern __shared__ __align__(128) char smem[];
    const uint32_t sb = smem_u32(smem);
    const int tid = threadIdx.x, lane = tid & 31, wid = tid >> 5;
    const int wm = wid >> 2, wn = wid & 3;
    const int bm = blockIdx.y * 128, bn = blockIdx.x * 128;
    constexpr uint32_t STAGE = NA * A_TILE1 + B_TILE1;

    const uint16_t* Ap[2] = {A1, A2};
    const int arow = tid >> 2, ac16 = tid & 3;
    const int brow = tid >> 4, bc16 = tid & 15;

    auto load_stage = [&](int slot, int k0) {
        uint32_t base = sb + slot * STAGE;
        #pragma unroll
        for (int p = 0; p < NA; p++) {
            uint32_t ab = base + p * A_TILE1;
            const uint16_t* g = Ap[p] + (size_t)(bm + arow) * K + k0 + ac16 * 8;
            cpasync16(ab + arow * A_STRIDE + ac16 * 16, g);
            cpasync16(ab + (arow + 64) * A_STRIDE + ac16 * 16, g + (size_t)64 * K);
        }
        {
            uint32_t bb = base + NA * A_TILE1;
            const uint16_t* g = B1 + (size_t)(k0 + brow) * N + bn + bc16 * 8;
            cpasync16(bb + brow * B_STRIDE + bc16 * 16, g);
            cpasync16(bb + (brow + 16) * B_STRIDE + bc16 * 16, g + (size_t)16 * N);
        }
        cp_commit();
    };

    const int iters = K / BK;
    #pragma unroll
    for (int s = 0; s < STAGES - 1; s++)
        load_stage(s, s * BK);

    float acc[4][4][4];
    #pragma unroll
    for (int i = 0; i < 4; i++)
        #pragma unroll
        for (int j = 0; j < 4; j++)
            #pragma unroll
            for (int r = 0; r < 4; r++) acc[i][j][r] = 0.0f;

    const int lrow = lane & 15;
    const int lcol = lane >> 4;

    for (int it = 0; it < iters; ++it) {
        cp_wait<STAGES - 2>();
        __syncthreads();
        if (it + STAGES - 1 < iters)
            load_stage((it + STAGES - 1) % STAGES, (it + STAGES - 1) * BK);

        uint32_t base = sb + (it % STAGES) * STAGE;
        #pragma unroll
        for (int ks = 0; ks < 2; ks++) {
            uint32_t bf[2][4];
            #pragma unroll
            for (int nt2 = 0; nt2 < 2; nt2++) {
                uint32_t addr = base + NA * A_TILE1
                              + (ks * 16 + lrow) * B_STRIDE
                              + (wn * 32 + nt2 * 16 + lcol * 8) * 2;
                ldsm4t(bf[nt2][0], bf[nt2][1], bf[nt2][2], bf[nt2][3], addr);
            }
            uint32_t afa[2][4], afb[2][4];
            auto lda = [&](uint32_t (&dst)[2][4], int mt) {
                #pragma unroll
                for (int p = 0; p < NA; p++) {
                    uint32_t addr = base + p * A_TILE1
                                  + (wm * 64 + mt * 16 + lrow) * A_STRIDE
                                  + ks * 32 + lcol * 16;
                    ldsm4(dst[p][0], dst[p][1], dst[p][2], dst[p][3], addr);
                }
            };
            auto mmarow = [&](float (&ar)[4][4], const uint32_t (&af)[2][4]) {
                #pragma unroll
                for (int nt = 0; nt < 4; nt++) {
                    const uint32_t* b0 = &bf[nt >> 1][(nt & 1) * 2];
                    mma16816(ar[nt], af[0], b0);
                    if (NA == 2) mma16816(ar[nt], af[1], b0);
                }
            };
            lda(afa, 0);
            lda(afb, 1);
            mmarow(acc[0], afa);
            lda(afa, 2);
            mmarow(acc[1], afb);
            lda(afb, 3);
            mmarow(acc[2], afa);
            mmarow(acc[3], afb);
        }
    }

    const int row0 = bm + wm * 64;
    const int col0 = bn + wn * 32;
    #pragma unroll
    for (int mt = 0; mt < 4; mt++)
        #pragma unroll
        for (int nt = 0; nt < 4; nt++) {
            int r = row0 + mt * 16 + (lane >> 2);
            int c = col0 + nt * 8 + (lane & 3) * 2;
            *(float2*)&C[(size_t)r * N + c]       = make_float2(acc[mt][nt][0], acc[mt][nt][1]);
            *(float2*)&C[(size_t)(r + 8) * N + c] = make_float2(acc[mt][nt][2], acc[mt][nt][3]);
        }
}

// ---------------- GEMM2 (fused): Y=adj@V, epilogue divides by Z and means heads -----
// V columns are head-interleaved (4d+h), so each CTA owns all 4 heads of 32 d-values.
// Epilogue: acc -> smem [row][h*33 + d] (conflict-free both sides), then
// out[bm+row][bx*32+d] = 0.25 * sum_h s[row][h*33+d] / Z[bm+row][h].
template <int STAGES>
__global__ void __launch_bounds__(256, 2)
gemm2_fused(const uint16_t* __restrict__ A1, const uint16_t* __restrict__ B1,
            const float4* __restrict__ Z4, float* __restrict__ out, int N, int K) {
    extern __shared__ __align__(128) char smem[];
    const uint32_t sb = smem_u32(smem);
    const int tid = threadIdx.x, lane = tid & 31, wid = tid >> 5;
    const int wm = wid >> 2, wn = wid & 3;
    const int bm = blockIdx.y * 128, bn = blockIdx.x * 128;
    constexpr uint32_t STAGE = A_TILE1 + B_TILE1;

    const int arow = tid >> 2, ac16 = tid & 3;
    const int brow = tid >> 4, bc16 = tid & 15;

    auto load_stage = [&](int slot, int k0) {
        uint32_t base = sb + slot * STAGE;
        {
            const uint16_t* g = A1 + (size_t)(bm + arow) * K + k0 + ac16 * 8;
            cpasync16(base + arow * A_STRIDE + ac16 * 16, g);
            cpasync16(base + (arow + 64) * A_STRIDE + ac16 * 16, g + (size_t)64 * K);
        }
        {
            uint32_t bb = base + A_TILE1;
            const uint16_t* g = B1 + (size_t)(k0 + brow) * N + bn + bc16 * 8;
            cpasync16(bb + brow * B_STRIDE + bc16 * 16, g);
            cpasync16(bb + (brow + 16) * B_STRIDE + bc16 * 16, g + (size_t)16 * N);
        }
        cp_commit();
    };

    const int iters = K / BK;
    #pragma unroll
    for (int s = 0; s < STAGES - 1; s++)
        load_stage(s, s * BK);

    float acc[4][4][4];
    #pragma unroll
    for (int i = 0; i < 4; i++)
        #pragma unroll
        for (int j = 0; j < 4; j++)
            #pragma unroll
            for (int r = 0; r < 4; r++) acc[i][j][r] = 0.0f;

    const int lrow = lane & 15;
    const int lcol = lane >> 4;

    for (int it = 0; it < iters; ++it) {
        cp_wait<STAGES - 2>();
        __syncthreads();
        if (it + STAGES - 1 < iters)
            load_stage((it + STAGES - 1) % STAGES, (it + STAGES - 1) * BK);

        uint32_t base = sb + (it % STAGES) * STAGE;
        #pragma unroll
        for (int ks = 0; ks < 2; ks++) {
            uint32_t bf[2][4];
            #pragma unroll
            for (int nt2 = 0; nt2 < 2; nt2++) {
                uint32_t addr = base + A_TILE1
                              + (ks * 16 + lrow) * B_STRIDE
                              + (wn * 32 + nt2 * 16 + lcol * 8) * 2;
                ldsm4t(bf[nt2][0], bf[nt2][1], bf[nt2][2], bf[nt2][3], addr);
            }
            uint32_t afa[4], afb[4];
            auto lda = [&](uint32_t (&dst)[4], int mt) {
                uint32_t addr = base + (wm * 64 + mt * 16 + lrow) * A_STRIDE
                              + ks * 32 + lcol * 16;
                ldsm4(dst[0], dst[1], dst[2], dst[3], addr);
            };
            auto mmarow = [&](float (&ar)[4][4], const uint32_t (&af)[4]) {
                #pragma unroll
                for (int nt = 0; nt < 4; nt++)
                    mma16816(ar[nt], af, &bf[nt >> 1][(nt & 1) * 2]);
            };
            lda(afa, 0);
            lda(afb, 1);
            mmarow(acc[0], afa);
            lda(afa, 2);
            mmarow(acc[1], afb);
            lda(afb, 3);
            mmarow(acc[2], afa);
            mmarow(acc[3], afb);
        }
    }

    // ---- fused epilogue ----
    cp_wait<0>();
    __syncthreads();                      // smem stages now reusable
    float* s = (float*)smem;              // [128][132]: col index = h*33 + d_local

    #pragma unroll
    for (int mt = 0; mt < 4; mt++)
        #pragma unroll
        for (int nt = 0; nt < 4; nt++) {
            int r = wm * 64 + mt * 16 + (lane >> 2);
            int c = wn * 32 + nt * 8 + (lane & 3) * 2;   // local col, even
            int h0 = c & 3, dl = c >> 2;                  // pair (c, c+1): h0, h0+1
            s[r * 132 + h0 * 33 + dl]             = acc[mt][nt][0];
            s[r * 132 + (h0 + 1) * 33 + dl]       = acc[mt][nt][1];
            s[(r + 8) * 132 + h0 * 33 + dl]       = acc[mt][nt][2];
            s[(r + 8) * 132 + (h0 + 1) * 33 + dl] = acc[mt][nt][3];
        }
    __syncthreads();

    #pragma unroll
    for (int i = 0; i < 16; i++) {
        int row = i * 8 + wid;            // 0..127
        int dl  = lane;                   // 0..31
        float4 z = Z4[bm + row];
        float v = s[row * 132 + 0 * 33 + dl] / z.x
                + s[row * 132 + 1 * 33 + dl] / z.y
                + s[row * 132 + 2 * 33 + dl] / z.z
                + s[row * 132 + 3 * 33 + dl] / z.w;
        out[(size_t)(bm + row) * N_HID + blockIdx.x * 32 + dl] = 0.25f * v;
    }
}

// ---------------- launch ----------------
extern "C" void kernel_launch(void* const* d_in, const int* in_sizes, int n_in,
                              void* d_out, int out_size) {
    const float* h = nullptr; const int* adj = nullptr;
    const float* W = nullptr; const float* a = nullptr;
    for (int i = 0; i < n_in; i++) {
        switch (in_sizes[i]) {
            case N_NODES * F_IN:      h   = (const float*)d_in[i]; break;
            case N_NODES * N_NODES:   adj = (const int*)d_in[i];   break;
            case F_IN * HD:           W   = (const float*)d_in[i]; break;
            case N_HEADS * 2 * N_HID: a   = (const float*)d_in[i]; break;
        }
    }
    float* out = (float*)d_out;

    uint16_t *hh, *hl, *Wh, *adjh, *V;
    float *HT, *tgt, *tmx;
    float4 *w4, *Z4;
    cudaGetSymbolAddress((void**)&hh,  g_hh);
    cudaGetSymbolAddress((void**)&hl,  g_hl);
    cudaGetSymbolAddress((void**)&Wh,  g_Wh);
    cudaGetSymbolAddress((void**)&adjh, g_adjh);
    cudaGetSymbolAddress((void**)&V,   g_V);
    cudaGetSymbolAddress((void**)&HT,  g_HT);
    cudaGetSymbolAddress((void**)&tgt, g_tgt);
    cudaGetSymbolAddress((void**)&tmx, g_tmax);
    cudaGetSymbolAddress((void**)&w4,  g_w4);
    cudaGetSymbolAddress((void**)&Z4,  g_Z4);

    const int smem1 = 3 * (2 * A_TILE1 + B_TILE1);   // 87552  (GEMM1: NA=2, S=3)
    const int smem2 = 4 * (A_TILE1 + B_TILE1);       // 75776  (GEMM2: S=4; epi needs 69.6K)
    const int smemz = 4 * N_NODES * 4;               // 65536  (zconv w planes)
    cudaFuncSetAttribute(gemm_mma<2, 3>, cudaFuncAttributeMaxDynamicSharedMemorySize, smem1);
    cudaFuncSetAttribute(gemm2_fused<4>, cudaFuncAttributeMaxDynamicSharedMemorySize, smem2);
    cudaFuncSetAttribute(zconv_kernel, cudaFuncAttributeMaxDynamicSharedMemorySize, smemz);

    // 1. operand prep
    split_h16<<<1024, 256>>>((const float4*)h, (uint4*)hh, (uint4*)hl);
    cvt_f16  <<<256, 256>>>((const float4*)W, (uint4*)Wh);

    // 2. GEMM1: HT = (hh+hl)@Wh (2 fp16 products)  M=4096 N=1024 K=512
    gemm_mma<2, 3><<<dim3(HD / 128, N_NODES / 128), 256, smem1>>>(
        hh, hl, Wh, HT, HD, F_IN);

    // 3. attention scalars
    tgt_kernel <<<2048, 256>>>(HT, a, tgt);
    tmax_kernel<<<N_HEADS, 256>>>(tgt, tmx);
    prew_kernel<<<16, 256>>>(tgt, tmx, w4);

    // 4. fused adjacency pass (adj -> adjh fp16 + exact Z) and weighted V
    zconv_kernel<<<N_NODES / 8, 256, smemz>>>(adj, w4, adjh, Z4);
    buildV      <<<N_NODES, 256>>>(HT, w4, (__half*)V);

    // 5. GEMM2 fused: out = mean_h( (adj@V)/Z )   M=4096 N=1024 K=4096
    gemm2_fused<4><<<dim3(HD / 128, N_NODES / 128), 256, smem2>>>(
        adjh, V, Z4, out, HD, N_NODES);

    (void)out_size;
}

// round 11
// speedup vs baseline: 1.2324x; 1.2324x over previous
#include <cuda_runtime.h>
#include <cuda_bf16.h>
#include <cuda_fp16.h>
#include <cstdint>

// ---------------- problem constants ----------------
#define N_NODES 4096
#define F_IN    512
#define N_HEADS 4
#define N_HID   256
#define HD      1024     // N_HEADS*N_HID
#define NP2     1152     // 1024 feature cols + 4 Z cols, padded to 9*128

// ---------------- scratch (device globals; allocation-free) ----------------
__device__ uint16_t g_hh [N_NODES * F_IN];             // fp16 h
__device__ uint16_t g_Wh [F_IN * HD];                  // fp16 W
__device__ uint16_t g_adjh[(size_t)N_NODES * N_NODES]; // fp16 adjacency {0,1}
__device__ uint16_t g_V  [(size_t)N_NODES * NP2];      // fp16 weighted V (+Z cols)
__device__ float    g_HT [N_NODES * HD];               // h@W fp32
__device__ float    g_Y  [(size_t)N_NODES * NP2];      // adj@V fp32
__device__ float    g_tgt [N_HEADS * N_NODES];
__device__ float    g_tmax[N_HEADS];
__device__ float4   g_w4 [N_NODES];                    // per-node head weights (scaled exp)

// ---------------- small helpers ----------------
__device__ __forceinline__ uint32_t smem_u32(const void* p) {
    uint32_t a;
    asm("{ .reg .u64 t; cvta.to.shared.u64 t, %1; cvt.u32.u64 %0, t; }" : "=r"(a) : "l"(p));
    return a;
}
__device__ __forceinline__ uint32_t pk(uint16_t a, uint16_t b) {
    return (uint32_t)a | ((uint32_t)b << 16);
}
__device__ __forceinline__ void cpasync16(uint32_t dst, const void* src) {
    asm volatile("cp.async.cg.shared.global [%0], [%1], 16;" :: "r"(dst), "l"(src));
}
__device__ __forceinline__ void cp_commit() {
    asm volatile("cp.async.commit_group;" ::: "memory");
}
template <int N>
__device__ __forceinline__ void cp_wait() {
    asm volatile("cp.async.wait_group %0;" :: "n"(N) : "memory");
}
__device__ __forceinline__ void ldsm4(uint32_t& r0, uint32_t& r1, uint32_t& r2, uint32_t& r3,
                                      uint32_t addr) {
    asm volatile("ldmatrix.sync.aligned.m8n8.x4.shared.b16 {%0,%1,%2,%3}, [%4];"
                 : "=r"(r0), "=r"(r1), "=r"(r2), "=r"(r3) : "r"(addr));
}
__device__ __forceinline__ void ldsm4t(uint32_t& r0, uint32_t& r1, uint32_t& r2, uint32_t& r3,
                                       uint32_t addr) {
    asm volatile("ldmatrix.sync.aligned.m8n8.x4.trans.shared.b16 {%0,%1,%2,%3}, [%4];"
                 : "=r"(r0), "=r"(r1), "=r"(r2), "=r"(r3) : "r"(addr));
}
__device__ __forceinline__ void mma16816(float* c, const uint32_t* a, const uint32_t* b) {
    asm volatile(
        "mma.sync.aligned.m16n8k16.row.col.f32.f16.f16.f32 "
        "{%0,%1,%2,%3},{%4,%5,%6,%7},{%8,%9},{%0,%1,%2,%3};"
        : "+f"(c[0]), "+f"(c[1]), "+f"(c[2]), "+f"(c[3])
        : "r"(a[0]), "r"(a[1]), "r"(a[2]), "r"(a[3]), "r"(b[0]), "r"(b[1]));
}

// ---------------- prep kernels ----------------
__global__ void cvt_f16(const float4* __restrict__ src, uint4* __restrict__ dst) {
    int i = blockIdx.x * 256 + threadIdx.x;
    float4 v0 = src[2 * i], v1 = src[2 * i + 1];
    float f[8] = {v0.x, v0.y, v0.z, v0.w, v1.x, v1.y, v1.z, v1.w};
    uint16_t H[8];
    #pragma unroll
    for (int j = 0; j < 8; j++) H[j] = __half_as_ushort(__float2half_rn(f[j]));
    dst[i] = make_uint4(pk(H[0], H[1]), pk(H[2], H[3]), pk(H[4], H[5]), pk(H[6], H[7]));
}

__global__ void prep_adj(const int4* __restrict__ adj, uint4* __restrict__ out) {
    int i = blockIdx.x * 256 + threadIdx.x;
    int4 a0 = adj[2 * i], a1 = adj[2 * i + 1];
    int v[8] = {a0.x, a0.y, a0.z, a0.w, a1.x, a1.y, a1.z, a1.w};
    uint16_t hv[8];
    #pragma unroll
    for (int j = 0; j < 8; j++) hv[j] = (v[j] > 0) ? (uint16_t)0x3C00 : (uint16_t)0;
    out[i] = make_uint4(pk(hv[0], hv[1]), pk(hv[2], hv[3]), pk(hv[4], hv[5]), pk(hv[6], hv[7]));
}

// tgt[h,m] = sum_d leaky_relu(HT[m,h*256+d]) * a[h*512+256+d]
// One warp per node m; fully coalesced HT row read; a staged in smem.
__global__ void tgt_kernel(const float* __restrict__ HT, const float* __restrict__ a,
                           float* __restrict__ tgt) {
    __shared__ float at[HD];   // at[h*256+d] = a[h*512+256+d]
    int tid = threadIdx.x, lane = tid & 31, wid = tid >> 5;
    #pragma unroll
    for (int k = 0; k < 4; k++) {
        int c = k * 256 + tid;
        at[c] = a[(c >> 8) * 512 + 256 + (c & 255)];
    }
    __syncthreads();
    int m = blockIdx.x * 8 + wid;
    const float4* row = (const float4*)(HT + (size_t)m * HD);
    float acc[4] = {0.f, 0.f, 0.f, 0.f};
    #pragma unroll
    for (int i = 0; i < 8; i++) {
        int c4 = i * 32 + lane;              // float4 index; c = 4*c4
        float4 x = row[c4];
        float4 av = *(const float4*)&at[c4 * 4];
        float v0 = (x.x > 0.f) ? x.x : 0.1f * x.x;
        float v1 = (x.y > 0.f) ? x.y : 0.1f * x.y;
        float v2 = (x.z > 0.f) ? x.z : 0.1f * x.z;
        float v3 = (x.w > 0.f) ? x.w : 0.1f * x.w;
        acc[i >> 1] += v0 * av.x + v1 * av.y + v2 * av.z + v3 * av.w;
    }
    #pragma unroll
    for (int o = 16; o; o >>= 1) {
        acc[0] += __shfl_xor_sync(0xFFFFFFFFu, acc[0], o);
        acc[1] += __shfl_xor_sync(0xFFFFFFFFu, acc[1], o);
        acc[2] += __shfl_xor_sync(0xFFFFFFFFu, acc[2], o);
        acc[3] += __shfl_xor_sync(0xFFFFFFFFu, acc[3], o);
    }
    if (lane < 4) tgt[lane * N_NODES + m] = acc[lane];
}

__global__ void tmax_kernel(const float* __restrict__ tgt, float* __restrict__ tmax) {
    int h = blockIdx.x;
    __shared__ float sm[256];
    float m = -1e30f;
    for (int i = threadIdx.x; i < N_NODES; i += 256)
        m = fmaxf(m, tgt[h * N_NODES + i]);
    sm[threadIdx.x] = m;
    __syncthreads();
    for (int s = 128; s; s >>= 1) {
        if (threadIdx.x < s) sm[threadIdx.x] = fmaxf(sm[threadIdx.x], sm[threadIdx.x + s]);
        __syncthreads();
    }
    if (threadIdx.x == 0) tmax[h] = sm[0];
}

// per-node head weights: w = exp(tgt - tmax) * 4096  (scale cancels in ratio)
__global__ void prew_kernel(const float* __restrict__ tgt, const float* __restrict__ tmax,
                            float4* __restrict__ w4) {
    int n = blockIdx.x * 256 + threadIdx.x;
    float4 w;
    w.x = expf(tgt[0 * N_NODES + n] - tmax[0]) * 4096.0f;
    w.y = expf(tgt[1 * N_NODES + n] - tmax[1]) * 4096.0f;
    w.z = expf(tgt[2 * N_NODES + n] - tmax[2]) * 4096.0f;
    w.w = expf(tgt[3 * N_NODES + n] - tmax[3]) * 4096.0f;
    w4[n] = w;
}

// V[n,c<1024] = w[h(c)]*HT[n,c];  V[n,1024+h] = w[h];  V[n,>=1028] = 0   (fp16)
__global__ void buildV(const float* __restrict__ HT, const float4* __restrict__ w4,
                       __half* __restrict__ V) {
    int n = blockIdx.x;
    float4 wv = w4[n];
    float wa[4] = {wv.x, wv.y, wv.z, wv.w};
    __half* row = V + (size_t)n * NP2;
    const float* ht = HT + (size_t)n * HD;
    for (int c = threadIdx.x; c < NP2; c += 256) {
        float v;
        if (c < HD)          v = wa[c >> 8] * ht[c];
        else if (c < HD + 4) v = wa[c - HD];
        else                 v = 0.0f;
        row[c] = __float2half(v);
    }
}

// out[n,d] = 0.25 * sum_h Y[n, h*256+d] / Y[n, 1024+h]
__global__ void final_kernel(const float* __restrict__ Y, float* __restrict__ out) {
    int i = blockIdx.x * 256 + threadIdx.x;
    int n = i >> 8, d = i & 255;
    const float* yr = Y + (size_t)n * NP2;
    float acc = 0.0f;
    #pragma unroll
    for (int h = 0; h < N_HEADS; h++)
        acc += yr[h * N_HID + d] / yr[HD + h];
    out[i] = 0.25f * acc;
}

// ---------------- shared GEMM geometry ----------------
#define BK 32
#define A_STRIDE 80                // bytes: 64B data + 16B pad per row
#define B_STRIDE 272               // bytes: 256B data + 16B pad per row
#define A_TILE1  (128 * A_STRIDE)  // 10240 B
#define B_TILE1  (BK * B_STRIDE)   // 8704 B

// ---------------- GEMM: BM=128 BN=128, 8 warps (2x4), warp 64x32, fp16 --------------
// Single product A1@B1; A-fragment ping-pong for LDS/TENSOR overlap (proven R9).
template <int STAGES>
__global__ void __launch_bounds__(256, 2)
gemm_mma(const uint16_t* __restrict__ A1, const uint16_t* __restrict__ B1,
         float* __restrict__ C, int N, int K) {
    extern __shared__ __align__(128) char smem[];
    const uint32_t sb = smem_u32(smem);
    const int tid = threadIdx.x, lane = tid & 31, wid = tid >> 5;
    const int wm = wid >> 2, wn = wid & 3;
    const int bm = blockIdx.y * 128, bn = blockIdx.x * 128;
    constexpr uint32_t STAGE = A_TILE1 + B_TILE1;

    const int arow = tid >> 2, ac16 = tid & 3;
    const int brow = tid >> 4, bc16 = tid & 15;

    auto load_stage = [&](int slot, int k0) {
        uint32_t base = sb + slot * STAGE;
        {
            const uint16_t* g = A1 + (size_t)(bm + arow) * K + k0 + ac16 * 8;
            cpasync16(base + arow * A_STRIDE + ac16 * 16, g);
            cpasync16(base + (arow + 64) * A_STRIDE + ac16 * 16, g + (size_t)64 * K);
        }
        {
            uint32_t bb = base + A_TILE1;
            const uint16_t* g = B1 + (size_t)(k0 + brow) * N + bn + bc16 * 8;
            cpasync16(bb + brow * B_STRIDE + bc16 * 16, g);
            cpasync16(bb + (brow + 16) * B_STRIDE + bc16 * 16, g + (size_t)16 * N);
        }
        cp_commit();
    };

    const int iters = K / BK;
    #pragma unroll
    for (int s = 0; s < STAGES - 1; s++)
        load_stage(s, s * BK);

    float acc[4][4][4];
    #pragma unroll
    for (int i = 0; i < 4; i++)
        #pragma unroll
        for (int j = 0; j < 4; j++)
            #pragma unroll
            for (int r = 0; r < 4; r++) acc[i][j][r] = 0.0f;

    const int lrow = lane & 15;
    const int lcol = lane >> 4;

    for (int it = 0; it < iters; ++it) {
        cp_wait<STAGES - 2>();
        __syncthreads();
        if (it + STAGES - 1 < iters)
            load_stage((it + STAGES - 1) % STAGES, (it + STAGES - 1) * BK);

        uint32_t base = sb + (it % STAGES) * STAGE;
        #pragma unroll
        for (int ks = 0; ks < 2; ks++) {
            uint32_t bf[2][4];
            #pragma unroll
            for (int nt2 = 0; nt2 < 2; nt2++) {
                uint32_t addr = base + A_TILE1
                              + (ks * 16 + lrow) * B_STRIDE
                              + (wn * 32 + nt2 * 16 + lcol * 8) * 2;
                ldsm4t(bf[nt2][0], bf[nt2][1], bf[nt2][2], bf[nt2][3], addr);
            }
            uint32_t afa[4], afb[4];
            auto lda = [&](uint32_t (&dst)[4], int mt) {
                uint32_t addr = base + (wm * 64 + mt * 16 + lrow) * A_STRIDE
                              + ks * 32 + lcol * 16;
                ldsm4(dst[0], dst[1], dst[2], dst[3], addr);
            };
            auto mmarow = [&](float (&ar)[4][4], const uint32_t (&af)[4]) {
                #pragma unroll
                for (int nt = 0; nt < 4; nt++)
                    mma16816(ar[nt], af, &bf[nt >> 1][(nt & 1) * 2]);
            };
            lda(afa, 0);
            lda(afb, 1);
            mmarow(acc[0], afa);
            lda(afa, 2);
            mmarow(acc[1], afb);
            lda(afb, 3);
            mmarow(acc[2], afa);
            mmarow(acc[3], afb);
        }
    }

    const int row0 = bm + wm * 64;
    const int col0 = bn + wn * 32;
    #pragma unroll
    for (int mt = 0; mt < 4; mt++)
        #pragma unroll
        for (int nt = 0; nt < 4; nt++) {
            int r = row0 + mt * 16 + (lane >> 2);
            int c = col0 + nt * 8 + (lane & 3) * 2;
            *(float2*)&C[(size_t)r * N + c]       = make_float2(acc[mt][nt][0], acc[mt][nt][1]);
            *(float2*)&C[(size_t)(r + 8) * N + c] = make_float2(acc[mt][nt][2], acc[mt][nt][3]);
        }
}

// ---------------- launch ----------------
extern "C" void kernel_launch(void* const* d_in, const int* in_sizes, int n_in,
                              void* d_out, int out_size) {
    const float* h = nullptr; const int* adj = nullptr;
    const float* W = nullptr; const float* a = nullptr;
    for (int i = 0; i < n_in; i++) {
        switch (in_sizes[i]) {
            case N_NODES * F_IN:      h   = (const float*)d_in[i]; break;
            case N_NODES * N_NODES:   adj = (const int*)d_in[i];   break;
            case F_IN * HD:           W   = (const float*)d_in[i]; break;
            case N_HEADS * 2 * N_HID: a   = (const float*)d_in[i]; break;
        }
    }
    float* out = (float*)d_out;

    uint16_t *hh, *Wh, *adjh, *V;
    float *HT, *Y, *tgt, *tmx;
    float4 *w4;
    cudaGetSymbolAddress((void**)&hh,  g_hh);
    cudaGetSymbolAddress((void**)&Wh,  g_Wh);
    cudaGetSymbolAddress((void**)&adjh, g_adjh);
    cudaGetSymbolAddress((void**)&V,   g_V);
    cudaGetSymbolAddress((void**)&HT,  g_HT);
    cudaGetSymbolAddress((void**)&Y,   g_Y);
    cudaGetSymbolAddress((void**)&tgt, g_tgt);
    cudaGetSymbolAddress((void**)&tmx, g_tmax);
    cudaGetSymbolAddress((void**)&w4,  g_w4);

    const int smem = 4 * (A_TILE1 + B_TILE1);       // 75776 (S=4, 2 CTA/SM)
    cudaFuncSetAttribute(gemm_mma<4>, cudaFuncAttributeMaxDynamicSharedMemorySize, smem);

    // 1. operand prep (h and W straight fp16; adjacency fp16)
    cvt_f16 <<<1024, 256>>>((const float4*)h, (uint4*)hh);
    cvt_f16 <<<256, 256>>>((const float4*)W, (uint4*)Wh);
    prep_adj<<<8192, 256>>>((const int4*)adj, (uint4*)adjh);

    // 2. GEMM1: HT = h@W (single fp16 product)  M=4096 N=1024 K=512
    gemm_mma<4><<<dim3(HD / 128, N_NODES / 128), 256, smem>>>(hh, Wh, HT, HD, F_IN);

    // 3. attention scalars + weighted V (Z weights folded in as columns 1024..1027)
    tgt_kernel <<<N_NODES / 8, 256>>>(HT, a, tgt);
    tmax_kernel<<<N_HEADS, 256>>>(tgt, tmx);
    prew_kernel<<<16, 256>>>(tgt, tmx, w4);
    buildV     <<<N_NODES, 256>>>(HT, w4, (__half*)V);

    // 4. GEMM2: Y = adj@V (fp16)  M=4096 N=1152 K=4096, 288 CTAs @ 2/SM
    gemm_mma<4><<<dim3(NP2 / 128, N_NODES / 128), 256, smem>>>(adjh, V, Y, NP2, N_NODES);

    // 5. normalize + head mean
    final_kernel<<<N_NODES, 256>>>(Y, out);
    (void)out_size;
}